// round 1
// baseline (speedup 1.0000x reference)
#include <cuda_runtime.h>
#include <cstdint>

#define EMBED 2048
#define SEQL 4096
#define NH 16
#define NKV 4
#define HD 128
#define KVC (NKV * HD)   // 512
#define WIN 512
#define SM_SCALE 0.08838834764831845f

// ---------------- scratch (allocation-free) ----------------
__device__ float g_Q[SEQL * EMBED];
__device__ float g_K[SEQL * KVC];
__device__ float g_V[SEQL * KVC];
__device__ float g_CTX[SEQL * EMBED];

// ---------------- packed f32x2 helpers (sm_100+) ----------------
__device__ __forceinline__ unsigned long long pk2(float x, float y) {
    unsigned long long r;
    asm("mov.b64 %0, {%1, %2};" : "=l"(r) : "f"(x), "f"(y));
    return r;
}
__device__ __forceinline__ void fma2(unsigned long long& c, unsigned long long a, unsigned long long b) {
    asm("fma.rn.f32x2 %0, %1, %2, %0;" : "+l"(c) : "l"(a), "l"(b));
}
__device__ __forceinline__ void mul2(unsigned long long& c, unsigned long long a) {
    asm("mul.rn.f32x2 %0, %0, %1;" : "+l"(c) : "l"(a));
}
__device__ __forceinline__ float2 upk(unsigned long long v) {
    float2 f;
    asm("mov.b64 {%0, %1}, %2;" : "=f"(f.x), "=f"(f.y) : "l"(v));
    return f;
}

// ---------------- GEMM: C[M,N] = A[M,K] @ B[N,K]^T + bias[N] ----------------
#define BM 128
#define BN 128
#define BK 16
#define LDT 132

__global__ __launch_bounds__(256, 2)
void gemm_bias_kernel(const float* __restrict__ A, const float* __restrict__ B,
                      const float* __restrict__ bias, float* __restrict__ C,
                      int M, int N, int K) {
    __shared__ float As[BK * LDT];
    __shared__ float Bs[BK * LDT];
    const int tid = threadIdx.x;
    const int tx = tid & 15, ty = tid >> 4;
    const int m0 = blockIdx.y * BM, n0 = blockIdx.x * BN;

    unsigned long long acc[8][4];
#pragma unroll
    for (int u = 0; u < 8; u++)
#pragma unroll
        for (int v = 0; v < 4; v++) acc[u][v] = 0ULL;  // (+0.0f, +0.0f)

    const int lrow = tid >> 2;        // 0..63 (plus +64 in second pass)
    const int lcol = (tid & 3) * 4;   // k offset within tile

    for (int k0 = 0; k0 < K; k0 += BK) {
#pragma unroll
        for (int i = 0; i < 2; i++) {
            int row = lrow + i * 64;
            float4 av = *(const float4*)(A + (size_t)(m0 + row) * K + k0 + lcol);
            As[(lcol + 0) * LDT + row] = av.x;
            As[(lcol + 1) * LDT + row] = av.y;
            As[(lcol + 2) * LDT + row] = av.z;
            As[(lcol + 3) * LDT + row] = av.w;
            float4 bv = *(const float4*)(B + (size_t)(n0 + row) * K + k0 + lcol);
            Bs[(lcol + 0) * LDT + row] = bv.x;
            Bs[(lcol + 1) * LDT + row] = bv.y;
            Bs[(lcol + 2) * LDT + row] = bv.z;
            Bs[(lcol + 3) * LDT + row] = bv.w;
        }
        __syncthreads();
#pragma unroll
        for (int kk = 0; kk < BK; kk++) {
            const float4 a0 = *(const float4*)&As[kk * LDT + ty * 8];
            const float4 a1 = *(const float4*)&As[kk * LDT + ty * 8 + 4];
            const ulonglong2 b0 = *(const ulonglong2*)&Bs[kk * LDT + tx * 8];
            const ulonglong2 b1 = *(const ulonglong2*)&Bs[kk * LDT + tx * 8 + 4];
            const float am[8] = {a0.x, a0.y, a0.z, a0.w, a1.x, a1.y, a1.z, a1.w};
            const unsigned long long bp[4] = {b0.x, b0.y, b1.x, b1.y};
#pragma unroll
            for (int u = 0; u < 8; u++) {
                unsigned long long ad = pk2(am[u], am[u]);
#pragma unroll
                for (int v = 0; v < 4; v++) fma2(acc[u][v], ad, bp[v]);
            }
        }
        __syncthreads();
    }

    float bvals[8];
#pragma unroll
    for (int j = 0; j < 8; j++) bvals[j] = bias[n0 + tx * 8 + j];
#pragma unroll
    for (int u = 0; u < 8; u++) {
        float o[8];
#pragma unroll
        for (int v = 0; v < 4; v++) {
            float2 p = upk(acc[u][v]);
            o[2 * v + 0] = p.x + bvals[2 * v + 0];
            o[2 * v + 1] = p.y + bvals[2 * v + 1];
        }
        float4* dst = (float4*)(C + (size_t)(m0 + ty * 8 + u) * N + n0 + tx * 8);
        dst[0] = make_float4(o[0], o[1], o[2], o[3]);
        dst[1] = make_float4(o[4], o[5], o[6], o[7]);
    }
}

// ---------------- sliding-window attention ----------------
// grid: (SEQL/64, NH); block: 256 threads
// smem: Qst[128][66] (transposed), Kst[128][66] (transposed), Vs[64][128], Ss[64][65]
#define TQ 64
#define TK 64
#define LQK 66
#define LSS 65
#define SMEM_ATTN ((2 * 128 * LQK + TK * HD + TQ * LSS) * (int)sizeof(float))

__global__ __launch_bounds__(256)
void attn_kernel(const float* __restrict__ Q, const float* __restrict__ K,
                 const float* __restrict__ V, float* __restrict__ CTX) {
    extern __shared__ float sh[];
    float* Qst = sh;                          // [e][q] stride LQK
    float* Kst = sh + 128 * LQK;              // [e][k] stride LQK
    float* Vs  = sh + 2 * 128 * LQK;          // [k][d] stride HD
    float* Ss  = sh + 2 * 128 * LQK + TK * HD; // [r][k] stride LSS

    const int tid = threadIdx.x;
    const int h = blockIdx.y;
    const int q0 = blockIdx.x * TQ;
    const int kvh = h >> 2;

    // load Q tile, transposed into shared
#pragma unroll
    for (int i = 0; i < 8; i++) {
        int id = tid + i * 256;
        int r = id >> 5;
        int c4 = (id & 31) * 4;
        float4 qv = *(const float4*)(Q + (size_t)(q0 + r) * EMBED + h * HD + c4);
        Qst[(c4 + 0) * LQK + r] = qv.x;
        Qst[(c4 + 1) * LQK + r] = qv.y;
        Qst[(c4 + 2) * LQK + r] = qv.z;
        Qst[(c4 + 3) * LQK + r] = qv.w;
    }

    const int ty = tid >> 4, tx = tid & 15;  // phase 1 (QK^T microtile)
    const int r2 = tid >> 2, c2 = tid & 3;   // phase 2 (softmax + PV)

    float m_i = -1e30f, l_i = 0.0f;
    unsigned long long ctx[16];
#pragma unroll
    for (int i = 0; i < 16; i++) ctx[i] = 0ULL;

    const int ktS = max(0, q0 - WIN) >> 6;
    const int ktE = q0 >> 6;

    for (int kt = ktS; kt <= ktE; kt++) {
        const int k0 = kt * TK;
        __syncthreads();  // prev phase-2 done before overwriting Kst/Vs/Ss
        // load K (transposed) and V tiles
#pragma unroll
        for (int i = 0; i < 8; i++) {
            int id = tid + i * 256;
            int r = id >> 5;
            int c4 = (id & 31) * 4;
            float4 kv = *(const float4*)(K + (size_t)(k0 + r) * KVC + kvh * HD + c4);
            Kst[(c4 + 0) * LQK + r] = kv.x;
            Kst[(c4 + 1) * LQK + r] = kv.y;
            Kst[(c4 + 2) * LQK + r] = kv.z;
            Kst[(c4 + 3) * LQK + r] = kv.w;
            float4 vv = *(const float4*)(V + (size_t)(k0 + r) * KVC + kvh * HD + c4);
            *(float4*)&Vs[r * HD + c4] = vv;
        }
        __syncthreads();

        // phase 1: S[64][64] = Q Kt^T (each thread 4x4)
        float s[4][4];
#pragma unroll
        for (int u = 0; u < 4; u++)
#pragma unroll
            for (int v = 0; v < 4; v++) s[u][v] = 0.0f;

#pragma unroll 8
        for (int e = 0; e < HD; e++) {
            float2 aa0 = *(const float2*)&Qst[e * LQK + ty * 4];
            float2 aa1 = *(const float2*)&Qst[e * LQK + ty * 4 + 2];
            float2 bb0 = *(const float2*)&Kst[e * LQK + tx * 4];
            float2 bb1 = *(const float2*)&Kst[e * LQK + tx * 4 + 2];
            const float a[4] = {aa0.x, aa0.y, aa1.x, aa1.y};
            const float b[4] = {bb0.x, bb0.y, bb1.x, bb1.y};
#pragma unroll
            for (int u = 0; u < 4; u++)
#pragma unroll
                for (int v = 0; v < 4; v++) s[u][v] += a[u] * b[v];
        }
#pragma unroll
        for (int u = 0; u < 4; u++) {
            const int qi = q0 + ty * 4 + u;
#pragma unroll
            for (int v = 0; v < 4; v++) {
                const int ki = k0 + tx * 4 + v;
                float val = (ki <= qi && ki + WIN >= qi) ? s[u][v] * SM_SCALE : -1e30f;
                Ss[(ty * 4 + u) * LSS + tx * 4 + v] = val;
            }
        }
        __syncthreads();

        // phase 2: online softmax + PV (thread: row r2, d-lane c2)
        float tmax = -1e30f;
#pragma unroll
        for (int k = 0; k < 16; k++)
            tmax = fmaxf(tmax, Ss[r2 * LSS + c2 * 16 + k]);
        tmax = fmaxf(tmax, __shfl_xor_sync(0xffffffffu, tmax, 1));
        tmax = fmaxf(tmax, __shfl_xor_sync(0xffffffffu, tmax, 2));
        const float m_new = fmaxf(m_i, tmax);
        const float scl = __expf(m_i - m_new);
        m_i = m_new;
        l_i *= scl;
        const unsigned long long s2 = pk2(scl, scl);
#pragma unroll
        for (int i = 0; i < 16; i++) mul2(ctx[i], s2);

#pragma unroll 4
        for (int k = 0; k < TK; k++) {
            const float p = __expf(Ss[r2 * LSS + k] - m_new);
            l_i += p;
            const unsigned long long pp = pk2(p, p);
            const unsigned long long* vrow = (const unsigned long long*)&Vs[k * HD];
#pragma unroll
            for (int i = 0; i < 16; i++) fma2(ctx[i], pp, vrow[c2 + 4 * i]);
        }
    }

    // write ctx / l  → CTX[s][h*HD + d]
    const float inv = 1.0f / l_i;
    float* dst = CTX + (size_t)(q0 + r2) * EMBED + h * HD;
#pragma unroll
    for (int i = 0; i < 16; i++) {
        float2 p = upk(ctx[i]);
        const int d = c2 * 2 + 8 * i;
        *(float2*)(dst + d) = make_float2(p.x * inv, p.y * inv);
    }
}

// ---------------- launch ----------------
extern "C" void kernel_launch(void* const* d_in, const int* in_sizes, int n_in,
                              void* d_out, int out_size) {
    const float* x    = (const float*)d_in[0];
    const float* wq_w = (const float*)d_in[1];
    const float* wq_b = (const float*)d_in[2];
    const float* wk_w = (const float*)d_in[3];
    const float* wk_b = (const float*)d_in[4];
    const float* wv_w = (const float*)d_in[5];
    const float* wv_b = (const float*)d_in[6];
    const float* wo_w = (const float*)d_in[7];
    const float* wo_b = (const float*)d_in[8];
    float* out = (float*)d_out;

    float *Qb, *Kb, *Vb, *Cb;
    cudaGetSymbolAddress((void**)&Qb, g_Q);
    cudaGetSymbolAddress((void**)&Kb, g_K);
    cudaGetSymbolAddress((void**)&Vb, g_V);
    cudaGetSymbolAddress((void**)&Cb, g_CTX);

    cudaFuncSetAttribute(attn_kernel, cudaFuncAttributeMaxDynamicSharedMemorySize, SMEM_ATTN);

    dim3 blk(256);
    gemm_bias_kernel<<<dim3(EMBED / BN, SEQL / BM), blk>>>(x, wq_w, wq_b, Qb, SEQL, EMBED, EMBED);
    gemm_bias_kernel<<<dim3(KVC / BN, SEQL / BM), blk>>>(x, wk_w, wk_b, Kb, SEQL, KVC, EMBED);
    gemm_bias_kernel<<<dim3(KVC / BN, SEQL / BM), blk>>>(x, wv_w, wv_b, Vb, SEQL, KVC, EMBED);
    attn_kernel<<<dim3(SEQL / TQ, NH), blk, SMEM_ATTN>>>(Qb, Kb, Vb, Cb);
    gemm_bias_kernel<<<dim3(EMBED / BN, SEQL / BM), blk>>>(Cb, wo_w, wo_b, out, SEQL, EMBED, EMBED);
}

// round 3
// speedup vs baseline: 1.5967x; 1.5967x over previous
#include <cuda_runtime.h>
#include <cuda_bf16.h>
#include <cstdint>

#define EMBED 2048
#define SEQL 4096
#define NH 16
#define NKV 4
#define HD 128
#define KVC (NKV * HD)   // 512
#define WIN 512
#define SM_SCALE 0.08838834764831845f

// ---------------- scratch (allocation-free) ----------------
__device__ float g_Q[SEQL * EMBED];
__device__ float g_K[SEQL * KVC];
__device__ float g_V[SEQL * KVC];
__device__ float g_CTX[SEQL * EMBED];

__device__ __align__(16) __nv_bfloat16 g_xh[SEQL * EMBED];
__device__ __align__(16) __nv_bfloat16 g_xl[SEQL * EMBED];
__device__ __align__(16) __nv_bfloat16 g_wqh[EMBED * EMBED];
__device__ __align__(16) __nv_bfloat16 g_wql[EMBED * EMBED];
__device__ __align__(16) __nv_bfloat16 g_wkh[KVC * EMBED];
__device__ __align__(16) __nv_bfloat16 g_wkl[KVC * EMBED];
__device__ __align__(16) __nv_bfloat16 g_wvh[KVC * EMBED];
__device__ __align__(16) __nv_bfloat16 g_wvl[KVC * EMBED];
__device__ __align__(16) __nv_bfloat16 g_woh[EMBED * EMBED];
__device__ __align__(16) __nv_bfloat16 g_wol[EMBED * EMBED];
__device__ __align__(16) __nv_bfloat16 g_ch[SEQL * EMBED];
__device__ __align__(16) __nv_bfloat16 g_cl[SEQL * EMBED];

// ---------------- helpers ----------------
__device__ __forceinline__ uint32_t smem_u32(const void* p) {
    uint32_t a;
    asm("{ .reg .u64 t; cvta.to.shared.u64 t, %1; cvt.u32.u64 %0, t; }" : "=r"(a) : "l"(p));
    return a;
}
__device__ __forceinline__ void cpasync16(uint32_t dst, const void* src) {
    asm volatile("cp.async.cg.shared.global [%0], [%1], 16;" :: "r"(dst), "l"(src));
}
__device__ __forceinline__ void ldsm4(uint32_t* r, uint32_t addr) {
    asm volatile("ldmatrix.sync.aligned.m8n8.x4.shared.b16 {%0,%1,%2,%3}, [%4];"
                 : "=r"(r[0]), "=r"(r[1]), "=r"(r[2]), "=r"(r[3]) : "r"(addr));
}
__device__ __forceinline__ void mma16816(float* c, const uint32_t* a, const uint32_t* b) {
    asm volatile("mma.sync.aligned.m16n8k16.row.col.f32.bf16.bf16.f32 "
                 "{%0,%1,%2,%3}, {%4,%5,%6,%7}, {%8,%9}, {%0,%1,%2,%3};"
                 : "+f"(c[0]), "+f"(c[1]), "+f"(c[2]), "+f"(c[3])
                 : "r"(a[0]), "r"(a[1]), "r"(a[2]), "r"(a[3]), "r"(b[0]), "r"(b[1]));
}

// ---------------- packed f32x2 helpers ----------------
__device__ __forceinline__ unsigned long long pk2(float x, float y) {
    unsigned long long r;
    asm("mov.b64 %0, {%1, %2};" : "=l"(r) : "f"(x), "f"(y));
    return r;
}
__device__ __forceinline__ void fma2(unsigned long long& c, unsigned long long a, unsigned long long b) {
    asm("fma.rn.f32x2 %0, %1, %2, %0;" : "+l"(c) : "l"(a), "l"(b));
}
__device__ __forceinline__ void mul2(unsigned long long& c, unsigned long long a) {
    asm("mul.rn.f32x2 %0, %0, %1;" : "+l"(c) : "l"(a));
}
__device__ __forceinline__ float2 upk(unsigned long long v) {
    float2 f;
    asm("mov.b64 {%0, %1}, %2;" : "=f"(f.x), "=f"(f.y) : "l"(v));
    return f;
}

// ---------------- fp32 -> bf16 hi/lo split ----------------
__global__ void cvt_hilo_kernel(const float* __restrict__ in, __nv_bfloat16* __restrict__ hi,
                                __nv_bfloat16* __restrict__ lo, int n4) {
    int i = blockIdx.x * blockDim.x + threadIdx.x;
    int stride = gridDim.x * blockDim.x;
    for (; i < n4; i += stride) {
        float4 v = ((const float4*)in)[i];
        __nv_bfloat16 h0 = __float2bfloat16(v.x);
        __nv_bfloat16 h1 = __float2bfloat16(v.y);
        __nv_bfloat16 h2 = __float2bfloat16(v.z);
        __nv_bfloat16 h3 = __float2bfloat16(v.w);
        __nv_bfloat16 l0 = __float2bfloat16(v.x - __bfloat162float(h0));
        __nv_bfloat16 l1 = __float2bfloat16(v.y - __bfloat162float(h1));
        __nv_bfloat16 l2 = __float2bfloat16(v.z - __bfloat162float(h2));
        __nv_bfloat16 l3 = __float2bfloat16(v.w - __bfloat162float(h3));
        ((__nv_bfloat162*)hi)[2 * i + 0] = __nv_bfloat162(h0, h1);
        ((__nv_bfloat162*)hi)[2 * i + 1] = __nv_bfloat162(h2, h3);
        ((__nv_bfloat162*)lo)[2 * i + 0] = __nv_bfloat162(l0, l1);
        ((__nv_bfloat162*)lo)[2 * i + 1] = __nv_bfloat162(l2, l3);
    }
}

// ---------------- mma.sync GEMM: C[M,N] = A[M,K] @ B[N,K]^T + bias ----------------
// bf16 hi/lo 3-pass (AhBh + AhBl + AlBh), fp32 accum. 128x128x32 tiles, 3-stage cp.async.
#define GBK 32
#define GRS 80                       // smem row stride bytes (32 bf16 = 64B data + 16B pad)
#define GTILE_B (128 * GRS)          // 10240
#define GSTAGE_B (4 * GTILE_B)       // 40960
#define GSMEM (3 * GSTAGE_B)         // 122880

__global__ __launch_bounds__(256, 1)
void gemm_mma_kernel(const __nv_bfloat16* __restrict__ Ah, const __nv_bfloat16* __restrict__ Al,
                     const __nv_bfloat16* __restrict__ Bh, const __nv_bfloat16* __restrict__ Bl,
                     const float* __restrict__ bias, float* __restrict__ C,
                     int M, int N, int K) {
    extern __shared__ char dsm[];
    const int tid = threadIdx.x;
    const int wid = tid >> 5, lane = tid & 31;
    const int m0 = blockIdx.y * 128, n0 = blockIdx.x * 128;
    const int wm = (wid >> 2) * 64;     // warp m offset in tile
    const int wn = (wid & 3) * 32;      // warp n offset in tile
    const int nch = K / GBK;

    const uint32_t smb = smem_u32(dsm);

    // per-thread load indices: 2 consecutive 16B segs per tile (4 tiles => 8 cp.async)
    const int rem0 = tid * 2;
    const int lrow = rem0 >> 2;          // 0..127
    const int lcg = rem0 & 3;            // 0 or 2
    const uint32_t ldoff0 = (uint32_t)(lrow * GRS + lcg * 16);
    const size_t gAoff = (size_t)(m0 + lrow) * K + lcg * 8;
    const size_t gBoff = (size_t)(n0 + lrow) * K + lcg * 8;

#define ISSUE_LOAD(c) do { \
        const int _k0 = (c) * GBK; \
        const uint32_t _sb = smb + ((c) % 3) * GSTAGE_B; \
        cpasync16(_sb + 0 * GTILE_B + ldoff0,      Ah + gAoff + _k0); \
        cpasync16(_sb + 0 * GTILE_B + ldoff0 + 16, Ah + gAoff + _k0 + 8); \
        cpasync16(_sb + 1 * GTILE_B + ldoff0,      Al + gAoff + _k0); \
        cpasync16(_sb + 1 * GTILE_B + ldoff0 + 16, Al + gAoff + _k0 + 8); \
        cpasync16(_sb + 2 * GTILE_B + ldoff0,      Bh + gBoff + _k0); \
        cpasync16(_sb + 2 * GTILE_B + ldoff0 + 16, Bh + gBoff + _k0 + 8); \
        cpasync16(_sb + 3 * GTILE_B + ldoff0,      Bl + gBoff + _k0); \
        cpasync16(_sb + 3 * GTILE_B + ldoff0 + 16, Bl + gBoff + _k0 + 8); \
    } while (0)

    float acc[4][4][4];
#pragma unroll
    for (int mt = 0; mt < 4; mt++)
#pragma unroll
        for (int nt = 0; nt < 4; nt++)
#pragma unroll
            for (int j = 0; j < 4; j++) acc[mt][nt][j] = 0.0f;

    // ldmatrix per-thread offsets
    const uint32_t a_off = (uint32_t)((wm + (lane & 15)) * GRS + ((lane >> 4) << 4));
    const uint32_t b_off = (uint32_t)((wn + (lane >> 4) * 8 + (lane & 7)) * GRS + ((lane >> 3) & 1) * 16);

    ISSUE_LOAD(0);
    asm volatile("cp.async.commit_group;" ::: "memory");
    ISSUE_LOAD(1);
    asm volatile("cp.async.commit_group;" ::: "memory");

    for (int c = 0; c < nch; c++) {
        __syncthreads();   // all warps done computing chunk c-1 (buffer reuse safety)
        if (c + 2 < nch) ISSUE_LOAD(c + 2);
        asm volatile("cp.async.commit_group;" ::: "memory");
        if (c + 2 < nch)      asm volatile("cp.async.wait_group 2;" ::: "memory");
        else if (c + 1 < nch) asm volatile("cp.async.wait_group 1;" ::: "memory");
        else                  asm volatile("cp.async.wait_group 0;" ::: "memory");
        __syncthreads();   // chunk c fully visible to all warps

        const uint32_t sb = smb + (c % 3) * GSTAGE_B;
        const uint32_t ahb = sb + 0 * GTILE_B;
        const uint32_t alb = sb + 1 * GTILE_B;
        const uint32_t bhb = sb + 2 * GTILE_B;
        const uint32_t blb = sb + 3 * GTILE_B;

#pragma unroll
        for (int ks = 0; ks < 2; ks++) {
            uint32_t ah[4][4], al[4][4], bh[2][4], bl[2][4];
#pragma unroll
            for (int mt = 0; mt < 4; mt++) {
                ldsm4(ah[mt], ahb + a_off + mt * (16 * GRS) + ks * 32);
                ldsm4(al[mt], alb + a_off + mt * (16 * GRS) + ks * 32);
            }
#pragma unroll
            for (int np = 0; np < 2; np++) {
                ldsm4(bh[np], bhb + b_off + np * (16 * GRS) + ks * 32);
                ldsm4(bl[np], blb + b_off + np * (16 * GRS) + ks * 32);
            }
#pragma unroll
            for (int mt = 0; mt < 4; mt++) {
#pragma unroll
                for (int nt = 0; nt < 4; nt++) {
                    const uint32_t* bhp = &bh[nt >> 1][(nt & 1) * 2];
                    const uint32_t* blp = &bl[nt >> 1][(nt & 1) * 2];
                    mma16816(acc[mt][nt], ah[mt], bhp);
                    mma16816(acc[mt][nt], al[mt], bhp);
                    mma16816(acc[mt][nt], ah[mt], blp);
                }
            }
        }
    }

    // epilogue: bias add + fp32 store
#pragma unroll
    for (int mt = 0; mt < 4; mt++) {
#pragma unroll
        for (int nt = 0; nt < 4; nt++) {
            const int r = m0 + wm + mt * 16 + (lane >> 2);
            const int cc = n0 + wn + nt * 8 + (lane & 3) * 2;
            const float b0 = bias[cc], b1 = bias[cc + 1];
            *(float2*)&C[(size_t)r * N + cc] =
                make_float2(acc[mt][nt][0] + b0, acc[mt][nt][1] + b1);
            *(float2*)&C[(size_t)(r + 8) * N + cc] =
                make_float2(acc[mt][nt][2] + b0, acc[mt][nt][3] + b1);
        }
    }
#undef ISSUE_LOAD
}

// ---------------- sliding-window attention (fp32 SIMT, unchanged) ----------------
#define TQ 64
#define TK 64
#define LQK 66
#define LSS 65
#define SMEM_ATTN ((2 * 128 * LQK + TK * HD + TQ * LSS) * (int)sizeof(float))

__global__ __launch_bounds__(256)
void attn_kernel(const float* __restrict__ Q, const float* __restrict__ K,
                 const float* __restrict__ V, float* __restrict__ CTX) {
    extern __shared__ float sh[];
    float* Qst = sh;
    float* Kst = sh + 128 * LQK;
    float* Vs  = sh + 2 * 128 * LQK;
    float* Ss  = sh + 2 * 128 * LQK + TK * HD;

    const int tid = threadIdx.x;
    const int h = blockIdx.y;
    const int q0 = blockIdx.x * TQ;
    const int kvh = h >> 2;

#pragma unroll
    for (int i = 0; i < 8; i++) {
        int id = tid + i * 256;
        int r = id >> 5;
        int c4 = (id & 31) * 4;
        float4 qv = *(const float4*)(Q + (size_t)(q0 + r) * EMBED + h * HD + c4);
        Qst[(c4 + 0) * LQK + r] = qv.x;
        Qst[(c4 + 1) * LQK + r] = qv.y;
        Qst[(c4 + 2) * LQK + r] = qv.z;
        Qst[(c4 + 3) * LQK + r] = qv.w;
    }

    const int ty = tid >> 4, tx = tid & 15;
    const int r2 = tid >> 2, c2 = tid & 3;

    float m_i = -1e30f, l_i = 0.0f;
    unsigned long long ctx[16];
#pragma unroll
    for (int i = 0; i < 16; i++) ctx[i] = 0ULL;

    const int ktS = max(0, q0 - WIN) >> 6;
    const int ktE = q0 >> 6;

    for (int kt = ktS; kt <= ktE; kt++) {
        const int k0 = kt * TK;
        __syncthreads();
#pragma unroll
        for (int i = 0; i < 8; i++) {
            int id = tid + i * 256;
            int r = id >> 5;
            int c4 = (id & 31) * 4;
            float4 kv = *(const float4*)(K + (size_t)(k0 + r) * KVC + kvh * HD + c4);
            Kst[(c4 + 0) * LQK + r] = kv.x;
            Kst[(c4 + 1) * LQK + r] = kv.y;
            Kst[(c4 + 2) * LQK + r] = kv.z;
            Kst[(c4 + 3) * LQK + r] = kv.w;
            float4 vv = *(const float4*)(V + (size_t)(k0 + r) * KVC + kvh * HD + c4);
            *(float4*)&Vs[r * HD + c4] = vv;
        }
        __syncthreads();

        float s[4][4];
#pragma unroll
        for (int u = 0; u < 4; u++)
#pragma unroll
            for (int v = 0; v < 4; v++) s[u][v] = 0.0f;

#pragma unroll 8
        for (int e = 0; e < HD; e++) {
            float2 aa0 = *(const float2*)&Qst[e * LQK + ty * 4];
            float2 aa1 = *(const float2*)&Qst[e * LQK + ty * 4 + 2];
            float2 bb0 = *(const float2*)&Kst[e * LQK + tx * 4];
            float2 bb1 = *(const float2*)&Kst[e * LQK + tx * 4 + 2];
            const float a[4] = {aa0.x, aa0.y, aa1.x, aa1.y};
            const float b[4] = {bb0.x, bb0.y, bb1.x, bb1.y};
#pragma unroll
            for (int u = 0; u < 4; u++)
#pragma unroll
                for (int v = 0; v < 4; v++) s[u][v] += a[u] * b[v];
        }
#pragma unroll
        for (int u = 0; u < 4; u++) {
            const int qi = q0 + ty * 4 + u;
#pragma unroll
            for (int v = 0; v < 4; v++) {
                const int ki = k0 + tx * 4 + v;
                float val = (ki <= qi && ki + WIN >= qi) ? s[u][v] * SM_SCALE : -1e30f;
                Ss[(ty * 4 + u) * LSS + tx * 4 + v] = val;
            }
        }
        __syncthreads();

        float tmax = -1e30f;
#pragma unroll
        for (int k = 0; k < 16; k++)
            tmax = fmaxf(tmax, Ss[r2 * LSS + c2 * 16 + k]);
        tmax = fmaxf(tmax, __shfl_xor_sync(0xffffffffu, tmax, 1));
        tmax = fmaxf(tmax, __shfl_xor_sync(0xffffffffu, tmax, 2));
        const float m_new = fmaxf(m_i, tmax);
        const float scl = __expf(m_i - m_new);
        m_i = m_new;
        l_i *= scl;
        const unsigned long long s2 = pk2(scl, scl);
#pragma unroll
        for (int i = 0; i < 16; i++) mul2(ctx[i], s2);

#pragma unroll 4
        for (int k = 0; k < TK; k++) {
            const float p = __expf(Ss[r2 * LSS + k] - m_new);
            l_i += p;
            const unsigned long long pp = pk2(p, p);
            const unsigned long long* vrow = (const unsigned long long*)&Vs[k * HD];
#pragma unroll
            for (int i = 0; i < 16; i++) fma2(ctx[i], pp, vrow[c2 + 4 * i]);
        }
    }

    const float inv = 1.0f / l_i;
    float* dst = CTX + (size_t)(q0 + r2) * EMBED + h * HD;
#pragma unroll
    for (int i = 0; i < 16; i++) {
        float2 p = upk(ctx[i]);
        const int d = c2 * 2 + 8 * i;
        *(float2*)(dst + d) = make_float2(p.x * inv, p.y * inv);
    }
}

// ---------------- launch ----------------
extern "C" void kernel_launch(void* const* d_in, const int* in_sizes, int n_in,
                              void* d_out, int out_size) {
    const float* x    = (const float*)d_in[0];
    const float* wq_w = (const float*)d_in[1];
    const float* wq_b = (const float*)d_in[2];
    const float* wk_w = (const float*)d_in[3];
    const float* wk_b = (const float*)d_in[4];
    const float* wv_w = (const float*)d_in[5];
    const float* wv_b = (const float*)d_in[6];
    const float* wo_w = (const float*)d_in[7];
    const float* wo_b = (const float*)d_in[8];
    float* out = (float*)d_out;

    float *Qb, *Kb, *Vb, *Cb;
    cudaGetSymbolAddress((void**)&Qb, g_Q);
    cudaGetSymbolAddress((void**)&Kb, g_K);
    cudaGetSymbolAddress((void**)&Vb, g_V);
    cudaGetSymbolAddress((void**)&Cb, g_CTX);

    __nv_bfloat16 *xh, *xl, *wqh, *wql, *wkh, *wkl, *wvh, *wvl, *woh, *wol, *ch, *cl;
    cudaGetSymbolAddress((void**)&xh, g_xh);
    cudaGetSymbolAddress((void**)&xl, g_xl);
    cudaGetSymbolAddress((void**)&wqh, g_wqh);
    cudaGetSymbolAddress((void**)&wql, g_wql);
    cudaGetSymbolAddress((void**)&wkh, g_wkh);
    cudaGetSymbolAddress((void**)&wkl, g_wkl);
    cudaGetSymbolAddress((void**)&wvh, g_wvh);
    cudaGetSymbolAddress((void**)&wvl, g_wvl);
    cudaGetSymbolAddress((void**)&woh, g_woh);
    cudaGetSymbolAddress((void**)&wol, g_wol);
    cudaGetSymbolAddress((void**)&ch, g_ch);
    cudaGetSymbolAddress((void**)&cl, g_cl);

    cudaFuncSetAttribute(attn_kernel, cudaFuncAttributeMaxDynamicSharedMemorySize, SMEM_ATTN);
    cudaFuncSetAttribute(gemm_mma_kernel, cudaFuncAttributeMaxDynamicSharedMemorySize, GSMEM);

    // fp32 -> bf16 hi/lo conversions
    cvt_hilo_kernel<<<1024, 256>>>(x, xh, xl, SEQL * EMBED / 4);
    cvt_hilo_kernel<<<1024, 256>>>(wq_w, wqh, wql, EMBED * EMBED / 4);
    cvt_hilo_kernel<<<256, 256>>>(wk_w, wkh, wkl, KVC * EMBED / 4);
    cvt_hilo_kernel<<<256, 256>>>(wv_w, wvh, wvl, KVC * EMBED / 4);
    cvt_hilo_kernel<<<1024, 256>>>(wo_w, woh, wol, EMBED * EMBED / 4);

    dim3 blk(256);
    gemm_mma_kernel<<<dim3(EMBED / 128, SEQL / 128), blk, GSMEM>>>(xh, xl, wqh, wql, wq_b, Qb, SEQL, EMBED, EMBED);
    gemm_mma_kernel<<<dim3(KVC / 128, SEQL / 128), blk, GSMEM>>>(xh, xl, wkh, wkl, wk_b, Kb, SEQL, KVC, EMBED);
    gemm_mma_kernel<<<dim3(KVC / 128, SEQL / 128), blk, GSMEM>>>(xh, xl, wvh, wvl, wv_b, Vb, SEQL, KVC, EMBED);

    attn_kernel<<<dim3(SEQL / TQ, NH), blk, SMEM_ATTN>>>(Qb, Kb, Vb, Cb);

    cvt_hilo_kernel<<<1024, 256>>>(Cb, ch, cl, SEQL * EMBED / 4);
    gemm_mma_kernel<<<dim3(EMBED / 128, SEQL / 128), blk, GSMEM>>>(ch, cl, woh, wol, wo_b, out, SEQL, EMBED, EMBED);
}

// round 5
// speedup vs baseline: 2.4283x; 1.5208x over previous
#include <cuda_runtime.h>
#include <cuda_bf16.h>
#include <cstdint>

#define EMBED 2048
#define SEQL 4096
#define NH 16
#define NKV 4
#define HD 128
#define KVC (NKV * HD)   // 512
#define WIN 512
#define SM_SCALE 0.08838834764831845f

// ---------------- scratch (allocation-free) ----------------
__device__ __align__(16) __nv_bfloat16 g_xh[SEQL * EMBED];
__device__ __align__(16) __nv_bfloat16 g_xl[SEQL * EMBED];
__device__ __align__(16) __nv_bfloat16 g_wqh[EMBED * EMBED];
__device__ __align__(16) __nv_bfloat16 g_wql[EMBED * EMBED];
__device__ __align__(16) __nv_bfloat16 g_wkh[KVC * EMBED];
__device__ __align__(16) __nv_bfloat16 g_wkl[KVC * EMBED];
__device__ __align__(16) __nv_bfloat16 g_wvh[KVC * EMBED];
__device__ __align__(16) __nv_bfloat16 g_wvl[KVC * EMBED];
__device__ __align__(16) __nv_bfloat16 g_woh[EMBED * EMBED];
__device__ __align__(16) __nv_bfloat16 g_wol[EMBED * EMBED];

__device__ __align__(16) __nv_bfloat16 g_qh[SEQL * EMBED];
__device__ __align__(16) __nv_bfloat16 g_ql[SEQL * EMBED];
__device__ __align__(16) __nv_bfloat16 g_kh[SEQL * KVC];
__device__ __align__(16) __nv_bfloat16 g_kl[SEQL * KVC];
__device__ __align__(16) __nv_bfloat16 g_vh[SEQL * KVC];
__device__ __align__(16) __nv_bfloat16 g_vl[SEQL * KVC];
__device__ __align__(16) __nv_bfloat16 g_ch[SEQL * EMBED];
__device__ __align__(16) __nv_bfloat16 g_cl[SEQL * EMBED];

// ---------------- helpers ----------------
__device__ __forceinline__ uint32_t smem_u32(const void* p) {
    uint32_t a;
    asm("{ .reg .u64 t; cvta.to.shared.u64 t, %1; cvt.u32.u64 %0, t; }" : "=r"(a) : "l"(p));
    return a;
}
__device__ __forceinline__ void cpasync16(uint32_t dst, const void* src) {
    asm volatile("cp.async.cg.shared.global [%0], [%1], 16;" :: "r"(dst), "l"(src));
}
__device__ __forceinline__ void ldsm4(uint32_t* r, uint32_t addr) {
    asm volatile("ldmatrix.sync.aligned.m8n8.x4.shared.b16 {%0,%1,%2,%3}, [%4];"
                 : "=r"(r[0]), "=r"(r[1]), "=r"(r[2]), "=r"(r[3]) : "r"(addr));
}
__device__ __forceinline__ void ldsm4t(uint32_t* r, uint32_t addr) {
    asm volatile("ldmatrix.sync.aligned.m8n8.x4.trans.shared.b16 {%0,%1,%2,%3}, [%4];"
                 : "=r"(r[0]), "=r"(r[1]), "=r"(r[2]), "=r"(r[3]) : "r"(addr));
}
__device__ __forceinline__ void mma16816(float* c, const uint32_t* a, const uint32_t* b) {
    asm volatile("mma.sync.aligned.m16n8k16.row.col.f32.bf16.bf16.f32 "
                 "{%0,%1,%2,%3}, {%4,%5,%6,%7}, {%8,%9}, {%0,%1,%2,%3};"
                 : "+f"(c[0]), "+f"(c[1]), "+f"(c[2]), "+f"(c[3])
                 : "r"(a[0]), "r"(a[1]), "r"(a[2]), "r"(a[3]), "r"(b[0]), "r"(b[1]));
}
// pack two fp32 into bf16x2 hi/lo pair (lower 16 bits = even column)
__device__ __forceinline__ void pack_hilo(float e0, float e1, uint32_t& ph, uint32_t& pl) {
    asm("cvt.rn.bf16x2.f32 %0, %1, %2;" : "=r"(ph) : "f"(e1), "f"(e0));
    float f1 = __uint_as_float(ph & 0xffff0000u);
    float f0 = __uint_as_float(ph << 16);
    asm("cvt.rn.bf16x2.f32 %0, %1, %2;" : "=r"(pl) : "f"(e1 - f1), "f"(e0 - f0));
}

// ---------------- fp32 -> bf16 hi/lo split ----------------
__global__ void cvt_hilo_kernel(const float* __restrict__ in, __nv_bfloat16* __restrict__ hi,
                                __nv_bfloat16* __restrict__ lo, int n4) {
    int i = blockIdx.x * blockDim.x + threadIdx.x;
    int stride = gridDim.x * blockDim.x;
    for (; i < n4; i += stride) {
        float4 v = ((const float4*)in)[i];
        uint32_t h0, l0, h1, l1;
        pack_hilo(v.x, v.y, h0, l0);
        pack_hilo(v.z, v.w, h1, l1);
        ((uint32_t*)hi)[2 * i + 0] = h0;
        ((uint32_t*)hi)[2 * i + 1] = h1;
        ((uint32_t*)lo)[2 * i + 0] = l0;
        ((uint32_t*)lo)[2 * i + 1] = l1;
    }
}

// ---------------- mma.sync GEMM: C[M,N] = A[M,K] @ B[N,K]^T + bias ----------------
#define GBK 32
#define GRS 80
#define GTILE_B (128 * GRS)
#define GSTAGE_B (4 * GTILE_B)
#define GSMEM (3 * GSTAGE_B)

__global__ __launch_bounds__(256, 1)
void gemm_mma_kernel(const __nv_bfloat16* __restrict__ Ah, const __nv_bfloat16* __restrict__ Al,
                     const __nv_bfloat16* __restrict__ Bh, const __nv_bfloat16* __restrict__ Bl,
                     const float* __restrict__ bias, float* __restrict__ C,
                     __nv_bfloat16* __restrict__ Chi, __nv_bfloat16* __restrict__ Clo,
                     int M, int N, int K) {
    extern __shared__ char dsm[];
    const int tid = threadIdx.x;
    const int wid = tid >> 5, lane = tid & 31;
    const int m0 = blockIdx.y * 128, n0 = blockIdx.x * 128;
    const int wm = (wid >> 2) * 64;
    const int wn = (wid & 3) * 32;
    const int nch = K / GBK;

    const uint32_t smb = smem_u32(dsm);

    const int rem0 = tid * 2;
    const int lrow = rem0 >> 2;
    const int lcg = rem0 & 3;
    const uint32_t ldoff0 = (uint32_t)(lrow * GRS + lcg * 16);
    const size_t gAoff = (size_t)(m0 + lrow) * K + lcg * 8;
    const size_t gBoff = (size_t)(n0 + lrow) * K + lcg * 8;

#define ISSUE_LOAD(c) do { \
        const int _k0 = (c) * GBK; \
        const uint32_t _sb = smb + ((c) % 3) * GSTAGE_B; \
        cpasync16(_sb + 0 * GTILE_B + ldoff0,      Ah + gAoff + _k0); \
        cpasync16(_sb + 0 * GTILE_B + ldoff0 + 16, Ah + gAoff + _k0 + 8); \
        cpasync16(_sb + 1 * GTILE_B + ldoff0,      Al + gAoff + _k0); \
        cpasync16(_sb + 1 * GTILE_B + ldoff0 + 16, Al + gAoff + _k0 + 8); \
        cpasync16(_sb + 2 * GTILE_B + ldoff0,      Bh + gBoff + _k0); \
        cpasync16(_sb + 2 * GTILE_B + ldoff0 + 16, Bh + gBoff + _k0 + 8); \
        cpasync16(_sb + 3 * GTILE_B + ldoff0,      Bl + gBoff + _k0); \
        cpasync16(_sb + 3 * GTILE_B + ldoff0 + 16, Bl + gBoff + _k0 + 8); \
    } while (0)

    float acc[4][4][4];
#pragma unroll
    for (int mt = 0; mt < 4; mt++)
#pragma unroll
        for (int nt = 0; nt < 4; nt++)
#pragma unroll
            for (int j = 0; j < 4; j++) acc[mt][nt][j] = 0.0f;

    const uint32_t a_off = (uint32_t)((wm + (lane & 15)) * GRS + ((lane >> 4) << 4));
    const uint32_t b_off = (uint32_t)((wn + (lane >> 4) * 8 + (lane & 7)) * GRS + ((lane >> 3) & 1) * 16);

    ISSUE_LOAD(0);
    asm volatile("cp.async.commit_group;" ::: "memory");
    ISSUE_LOAD(1);
    asm volatile("cp.async.commit_group;" ::: "memory");

    for (int c = 0; c < nch; c++) {
        __syncthreads();
        if (c + 2 < nch) ISSUE_LOAD(c + 2);
        asm volatile("cp.async.commit_group;" ::: "memory");
        if (c + 2 < nch)      asm volatile("cp.async.wait_group 2;" ::: "memory");
        else if (c + 1 < nch) asm volatile("cp.async.wait_group 1;" ::: "memory");
        else                  asm volatile("cp.async.wait_group 0;" ::: "memory");
        __syncthreads();

        const uint32_t sb = smb + (c % 3) * GSTAGE_B;
        const uint32_t ahb = sb + 0 * GTILE_B;
        const uint32_t alb = sb + 1 * GTILE_B;
        const uint32_t bhb = sb + 2 * GTILE_B;
        const uint32_t blb = sb + 3 * GTILE_B;

#pragma unroll
        for (int ks = 0; ks < 2; ks++) {
            uint32_t ah[4][4], al[4][4], bh[2][4], bl[2][4];
#pragma unroll
            for (int mt = 0; mt < 4; mt++) {
                ldsm4(ah[mt], ahb + a_off + mt * (16 * GRS) + ks * 32);
                ldsm4(al[mt], alb + a_off + mt * (16 * GRS) + ks * 32);
            }
#pragma unroll
            for (int np = 0; np < 2; np++) {
                ldsm4(bh[np], bhb + b_off + np * (16 * GRS) + ks * 32);
                ldsm4(bl[np], blb + b_off + np * (16 * GRS) + ks * 32);
            }
#pragma unroll
            for (int mt = 0; mt < 4; mt++) {
#pragma unroll
                for (int nt = 0; nt < 4; nt++) {
                    const uint32_t* bhp = &bh[nt >> 1][(nt & 1) * 2];
                    const uint32_t* blp = &bl[nt >> 1][(nt & 1) * 2];
                    mma16816(acc[mt][nt], ah[mt], bhp);
                    mma16816(acc[mt][nt], al[mt], bhp);
                    mma16816(acc[mt][nt], ah[mt], blp);
                }
            }
        }
    }

    // epilogue: bias add; write fp32 OR bf16 hi/lo
#pragma unroll
    for (int mt = 0; mt < 4; mt++) {
#pragma unroll
        for (int nt = 0; nt < 4; nt++) {
            const int r = m0 + wm + mt * 16 + (lane >> 2);
            const int cc = n0 + wn + nt * 8 + (lane & 3) * 2;
            const float b0 = bias[cc], b1 = bias[cc + 1];
            float o0 = acc[mt][nt][0] + b0, o1 = acc[mt][nt][1] + b1;
            float o2 = acc[mt][nt][2] + b0, o3 = acc[mt][nt][3] + b1;
            if (Chi) {
                uint32_t ph, pl;
                pack_hilo(o0, o1, ph, pl);
                *(uint32_t*)&Chi[(size_t)r * N + cc] = ph;
                *(uint32_t*)&Clo[(size_t)r * N + cc] = pl;
                pack_hilo(o2, o3, ph, pl);
                *(uint32_t*)&Chi[(size_t)(r + 8) * N + cc] = ph;
                *(uint32_t*)&Clo[(size_t)(r + 8) * N + cc] = pl;
            } else {
                *(float2*)&C[(size_t)r * N + cc] = make_float2(o0, o1);
                *(float2*)&C[(size_t)(r + 8) * N + cc] = make_float2(o2, o3);
            }
        }
    }
#undef ISSUE_LOAD
}

// ---------------- tensor-core sliding-window attention ----------------
// CTA: 128 q-rows x 1 head. 8 warps x 16 rows. K/V tiles of 64 keys, double buffered.
#define AQ 128
#define AK 64
#define ARS 272                       // 128 bf16 = 256B + 16B pad
#define ATILE (64 * ARS)              // 17408
#define AQTILE (128 * ARS)            // 34816
#define AQ_BYTES (2 * AQTILE)         // 69632
#define AKV_STAGE (4 * ATILE)         // 69632
#define ASMEM (AQ_BYTES + 2 * AKV_STAGE)  // 208896

__global__ __launch_bounds__(256, 1)
void attn_mma_kernel(const __nv_bfloat16* __restrict__ Qhg, const __nv_bfloat16* __restrict__ Qlg,
                     const __nv_bfloat16* __restrict__ Khg, const __nv_bfloat16* __restrict__ Klg,
                     const __nv_bfloat16* __restrict__ Vhg, const __nv_bfloat16* __restrict__ Vlg,
                     __nv_bfloat16* __restrict__ Ch, __nv_bfloat16* __restrict__ Cl) {
    extern __shared__ char sm_[];
    const int tid = threadIdx.x, wid = tid >> 5, lane = tid & 31;
    const int h = blockIdx.y;
    const int q0 = blockIdx.x * AQ;
    const int kvh = h >> 2;

    const uint32_t smb = smem_u32(sm_);
    const uint32_t qh_b = smb, ql_b = smb + AQTILE;
    const uint32_t kv_b = smb + AQ_BYTES;

    // ---- issue Q loads (hi/lo): 128 rows x 16 segs x 2 tensors, 2 threads/row ----
    {
        const int row = tid >> 1;
        const int s0 = (tid & 1) * 8;
        const __nv_bfloat16* gqh = Qhg + (size_t)(q0 + row) * EMBED + h * HD + s0 * 8;
        const __nv_bfloat16* gql = Qlg + (size_t)(q0 + row) * EMBED + h * HD + s0 * 8;
        const uint32_t soff = (uint32_t)(row * ARS + s0 * 16);
#pragma unroll
        for (int s = 0; s < 8; s++) {
            cpasync16(qh_b + soff + s * 16, gqh + s * 8);
            cpasync16(ql_b + soff + s * 16, gql + s * 8);
        }
    }

    // KV loader: tensor = tid>>6 (Kh,Kl,Vh,Vl), row = tid&63, FULL 16 segs (256B/row)
    const int lt = tid >> 6;
    const int lrow = tid & 63;
    const __nv_bfloat16* ltp = (lt == 0) ? Khg : (lt == 1) ? Klg : (lt == 2) ? Vhg : Vlg;
    const uint32_t lso = (uint32_t)(lt * ATILE + lrow * ARS);

#define ISSUE_KV(kt, stage) do { \
        const __nv_bfloat16* _g = ltp + (size_t)((kt) * AK + lrow) * KVC + kvh * HD; \
        const uint32_t _sb = kv_b + (stage) * AKV_STAGE + lso; \
        _Pragma("unroll") \
        for (int _s = 0; _s < 16; _s++) cpasync16(_sb + _s * 16, _g + _s * 8); \
    } while (0)

    const int ktS = (q0 >= WIN) ? ((q0 - WIN) >> 6) : 0;
    const int ktE = (q0 + AQ - 64) >> 6;

    ISSUE_KV(ktS, 0);
    asm volatile("cp.async.commit_group;" ::: "memory");   // G0: Q + KV(ktS)
    if (ktS + 1 <= ktE) ISSUE_KV(ktS + 1, 1);
    asm volatile("cp.async.commit_group;" ::: "memory");   // G1
    asm volatile("cp.async.wait_group 1;" ::: "memory");   // G0 done
    __syncthreads();

    // fragment addresses
    const uint32_t a_off = (uint32_t)((wid * 16 + (lane & 15)) * ARS + ((lane >> 4) << 4));
    const uint32_t b_off = (uint32_t)(((lane & 7) + ((lane >> 4) << 3)) * ARS + ((lane >> 3) & 1) * 16);
    const uint32_t v_off = (uint32_t)((lane & 15) * ARS + ((lane >> 4) << 4));

    float m0r = -1e30f, m1r = -1e30f, l0r = 0.0f, l1r = 0.0f;
    float O[16][4];
#pragma unroll
    for (int i = 0; i < 16; i++)
#pragma unroll
        for (int j = 0; j < 4; j++) O[i][j] = 0.0f;

    const int qi0 = q0 + wid * 16 + (lane >> 2);
    const int qi1 = qi0 + 8;

    for (int kt = ktS; kt <= ktE; kt++) {
        const int stage = (kt - ktS) & 1;
        const uint32_t kh_b = kv_b + stage * AKV_STAGE;
        const uint32_t kl_b = kh_b + ATILE;
        const uint32_t vh_b = kh_b + 2 * ATILE;
        const uint32_t vl_b = kh_b + 3 * ATILE;
        const int k0 = kt * AK;

        // ---- S = Q K^T (3-pass hi/lo) ----
        float sc[8][4];
#pragma unroll
        for (int i = 0; i < 8; i++)
#pragma unroll
            for (int j = 0; j < 4; j++) sc[i][j] = 0.0f;

#pragma unroll
        for (int ks = 0; ks < 8; ks++) {
            uint32_t qa[4], ql4[4];
            ldsm4(qa, qh_b + a_off + ks * 32);
            ldsm4(ql4, ql_b + a_off + ks * 32);
#pragma unroll
            for (int np = 0; np < 4; np++) {
                uint32_t kh4[4], kl4[4];
                ldsm4(kh4, kh_b + b_off + np * (16 * ARS) + ks * 32);
                ldsm4(kl4, kl_b + b_off + np * (16 * ARS) + ks * 32);
                mma16816(sc[2 * np], qa, &kh4[0]);
                mma16816(sc[2 * np], ql4, &kh4[0]);
                mma16816(sc[2 * np], qa, &kl4[0]);
                mma16816(sc[2 * np + 1], qa, &kh4[2]);
                mma16816(sc[2 * np + 1], ql4, &kh4[2]);
                mma16816(sc[2 * np + 1], qa, &kl4[2]);
            }
        }

        // ---- mask + scale ----
#pragma unroll
        for (int nt = 0; nt < 8; nt++) {
            const int kib = k0 + nt * 8 + (lane & 3) * 2;
#pragma unroll
            for (int j = 0; j < 4; j++) {
                const int kij = kib + (j & 1);
                const int qij = (j >> 1) ? qi1 : qi0;
                const bool ok = (kij <= qij) && (kij + WIN >= qij);
                sc[nt][j] = ok ? sc[nt][j] * SM_SCALE : -1e30f;
            }
        }

        // ---- online softmax ----
        float t0 = -1e30f, t1 = -1e30f;
#pragma unroll
        for (int nt = 0; nt < 8; nt++) {
            t0 = fmaxf(t0, fmaxf(sc[nt][0], sc[nt][1]));
            t1 = fmaxf(t1, fmaxf(sc[nt][2], sc[nt][3]));
        }
        t0 = fmaxf(t0, __shfl_xor_sync(0xffffffffu, t0, 1));
        t0 = fmaxf(t0, __shfl_xor_sync(0xffffffffu, t0, 2));
        t1 = fmaxf(t1, __shfl_xor_sync(0xffffffffu, t1, 1));
        t1 = fmaxf(t1, __shfl_xor_sync(0xffffffffu, t1, 2));
        const float mn0 = fmaxf(fmaxf(m0r, t0), -80.0f);
        const float mn1 = fmaxf(fmaxf(m1r, t1), -80.0f);
        const float scl0 = __expf(m0r - mn0);
        const float scl1 = __expf(m1r - mn1);
        m0r = mn0; m1r = mn1;
        l0r *= scl0; l1r *= scl1;
#pragma unroll
        for (int nt = 0; nt < 16; nt++) {
            O[nt][0] *= scl0; O[nt][1] *= scl0;
            O[nt][2] *= scl1; O[nt][3] *= scl1;
        }
        float ls0 = 0.0f, ls1 = 0.0f;
#pragma unroll
        for (int nt = 0; nt < 8; nt++) {
            sc[nt][0] = __expf(sc[nt][0] - mn0);
            sc[nt][1] = __expf(sc[nt][1] - mn0);
            sc[nt][2] = __expf(sc[nt][2] - mn1);
            sc[nt][3] = __expf(sc[nt][3] - mn1);
            ls0 += sc[nt][0] + sc[nt][1];
            ls1 += sc[nt][2] + sc[nt][3];
        }
        l0r += ls0; l1r += ls1;

        // ---- pack P into A-fragments (hi/lo) ----
        uint32_t pah[4][4], pal[4][4];
#pragma unroll
        for (int ks = 0; ks < 4; ks++) {
            pack_hilo(sc[2 * ks][0], sc[2 * ks][1], pah[ks][0], pal[ks][0]);
            pack_hilo(sc[2 * ks][2], sc[2 * ks][3], pah[ks][1], pal[ks][1]);
            pack_hilo(sc[2 * ks + 1][0], sc[2 * ks + 1][1], pah[ks][2], pal[ks][2]);
            pack_hilo(sc[2 * ks + 1][2], sc[2 * ks + 1][3], pah[ks][3], pal[ks][3]);
        }

        // ---- O += P V (3-pass hi/lo) ----
#pragma unroll
        for (int ks = 0; ks < 4; ks++) {
#pragma unroll
            for (int dp = 0; dp < 8; dp++) {
                uint32_t vh4[4], vl4[4];
                ldsm4t(vh4, vh_b + v_off + ks * (16 * ARS) + dp * 32);
                ldsm4t(vl4, vl_b + v_off + ks * (16 * ARS) + dp * 32);
                mma16816(O[2 * dp], pah[ks], &vh4[0]);
                mma16816(O[2 * dp], pal[ks], &vh4[0]);
                mma16816(O[2 * dp], pah[ks], &vl4[0]);
                mma16816(O[2 * dp + 1], pah[ks], &vh4[2]);
                mma16816(O[2 * dp + 1], pal[ks], &vh4[2]);
                mma16816(O[2 * dp + 1], pah[ks], &vl4[2]);
            }
        }

        // ---- pipeline ----
        __syncthreads();
        if (kt + 2 <= ktE) ISSUE_KV(kt + 2, stage);
        asm volatile("cp.async.commit_group;" ::: "memory");
        if (kt + 2 <= ktE) asm volatile("cp.async.wait_group 1;" ::: "memory");
        else               asm volatile("cp.async.wait_group 0;" ::: "memory");
        __syncthreads();
    }
#undef ISSUE_KV

    // ---- epilogue: finish l reduction, normalize, write bf16 hi/lo ctx ----
    l0r += __shfl_xor_sync(0xffffffffu, l0r, 1);
    l0r += __shfl_xor_sync(0xffffffffu, l0r, 2);
    l1r += __shfl_xor_sync(0xffffffffu, l1r, 1);
    l1r += __shfl_xor_sync(0xffffffffu, l1r, 2);
    const float inv0 = 1.0f / l0r, inv1 = 1.0f / l1r;
    const size_t r0off = (size_t)qi0 * EMBED + h * HD;
    const size_t r1off = (size_t)qi1 * EMBED + h * HD;
#pragma unroll
    for (int nt = 0; nt < 16; nt++) {
        const int d = nt * 8 + (lane & 3) * 2;
        uint32_t ph, pl;
        pack_hilo(O[nt][0] * inv0, O[nt][1] * inv0, ph, pl);
        *(uint32_t*)&Ch[r0off + d] = ph;
        *(uint32_t*)&Cl[r0off + d] = pl;
        pack_hilo(O[nt][2] * inv1, O[nt][3] * inv1, ph, pl);
        *(uint32_t*)&Ch[r1off + d] = ph;
        *(uint32_t*)&Cl[r1off + d] = pl;
    }
}

// ---------------- launch ----------------
extern "C" void kernel_launch(void* const* d_in, const int* in_sizes, int n_in,
                              void* d_out, int out_size) {
    const float* x    = (const float*)d_in[0];
    const float* wq_w = (const float*)d_in[1];
    const float* wq_b = (const float*)d_in[2];
    const float* wk_w = (const float*)d_in[3];
    const float* wk_b = (const float*)d_in[4];
    const float* wv_w = (const float*)d_in[5];
    const float* wv_b = (const float*)d_in[6];
    const float* wo_w = (const float*)d_in[7];
    const float* wo_b = (const float*)d_in[8];
    float* out = (float*)d_out;

    __nv_bfloat16 *xh, *xl, *wqh, *wql, *wkh, *wkl, *wvh, *wvl, *woh, *wol;
    __nv_bfloat16 *qh, *ql, *kh, *kl, *vh, *vl, *ch, *cl;
    cudaGetSymbolAddress((void**)&xh, g_xh);
    cudaGetSymbolAddress((void**)&xl, g_xl);
    cudaGetSymbolAddress((void**)&wqh, g_wqh);
    cudaGetSymbolAddress((void**)&wql, g_wql);
    cudaGetSymbolAddress((void**)&wkh, g_wkh);
    cudaGetSymbolAddress((void**)&wkl, g_wkl);
    cudaGetSymbolAddress((void**)&wvh, g_wvh);
    cudaGetSymbolAddress((void**)&wvl, g_wvl);
    cudaGetSymbolAddress((void**)&woh, g_woh);
    cudaGetSymbolAddress((void**)&wol, g_wol);
    cudaGetSymbolAddress((void**)&qh, g_qh);
    cudaGetSymbolAddress((void**)&ql, g_ql);
    cudaGetSymbolAddress((void**)&kh, g_kh);
    cudaGetSymbolAddress((void**)&kl, g_kl);
    cudaGetSymbolAddress((void**)&vh, g_vh);
    cudaGetSymbolAddress((void**)&vl, g_vl);
    cudaGetSymbolAddress((void**)&ch, g_ch);
    cudaGetSymbolAddress((void**)&cl, g_cl);

    cudaFuncSetAttribute(gemm_mma_kernel, cudaFuncAttributeMaxDynamicSharedMemorySize, GSMEM);
    cudaFuncSetAttribute(attn_mma_kernel, cudaFuncAttributeMaxDynamicSharedMemorySize, ASMEM);

    // fp32 -> bf16 hi/lo conversions (inputs + weights only)
    cvt_hilo_kernel<<<1024, 256>>>(x, xh, xl, SEQL * EMBED / 4);
    cvt_hilo_kernel<<<1024, 256>>>(wq_w, wqh, wql, EMBED * EMBED / 4);
    cvt_hilo_kernel<<<256, 256>>>(wk_w, wkh, wkl, KVC * EMBED / 4);
    cvt_hilo_kernel<<<256, 256>>>(wv_w, wvh, wvl, KVC * EMBED / 4);
    cvt_hilo_kernel<<<1024, 256>>>(wo_w, woh, wol, EMBED * EMBED / 4);

    dim3 blk(256);
    // projections write bf16 hi/lo directly
    gemm_mma_kernel<<<dim3(EMBED / 128, SEQL / 128), blk, GSMEM>>>(xh, xl, wqh, wql, wq_b, nullptr, qh, ql, SEQL, EMBED, EMBED);
    gemm_mma_kernel<<<dim3(KVC / 128, SEQL / 128), blk, GSMEM>>>(xh, xl, wkh, wkl, wk_b, nullptr, kh, kl, SEQL, KVC, EMBED);
    gemm_mma_kernel<<<dim3(KVC / 128, SEQL / 128), blk, GSMEM>>>(xh, xl, wvh, wvl, wv_b, nullptr, vh, vl, SEQL, KVC, EMBED);

    attn_mma_kernel<<<dim3(SEQL / AQ, NH), blk, ASMEM>>>(qh, ql, kh, kl, vh, vl, ch, cl);

    // output projection writes fp32 result
    gemm_mma_kernel<<<dim3(EMBED / 128, SEQL / 128), blk, GSMEM>>>(ch, cl, woh, wol, wo_b, out, nullptr, nullptr, SEQL, EMBED, EMBED);
}